// round 14
// baseline (speedup 1.0000x reference)
#include <cuda_runtime.h>

// Problem constants
#define T_STEPS 512
#define B_TOTAL 512
#define I_DIM   32
#define H_DIM   64
#define G_DIM   256   // 4*H
#define HX_DIM  96    // concatenated [h(64); x(32)]
#define NT      8     // num tickers

typedef unsigned long long u64;

__device__ __forceinline__ u64 pack2(float lo, float hi) {
    u64 d;
    asm("mov.b64 %0, {%1, %2};" : "=l"(d) : "f"(lo), "f"(hi));
    return d;
}
__device__ __forceinline__ void unpack2(u64 v, float& lo, float& hi) {
    asm("mov.b64 {%0, %1}, %2;" : "=f"(lo), "=f"(hi) : "l"(v));
}
__device__ __forceinline__ float ex2f(float x) {
    float r;
    asm("ex2.approx.f32 %0, %1;" : "=f"(r) : "f"(x));
    return r;
}
__device__ __forceinline__ float rcpf(float x) {
    float r;
    asm("rcp.approx.f32 %0, %1;" : "=f"(r) : "f"(x));
    return r;
}
#define L2E 1.4426950408889634f

// ---------------------------------------------------------------------------
// Fused LSTM: scalar-FFMA matvec (R13) + smem-free quad-shfl combine (R10)
// = ONE barrier per step.
// 256 CTAs x 256 threads, 2 batches/CTA, 2 CTAs/SM.
// Thread (cell = tid>>2, gq = tid&3) owns gate row gq*64+cell:
//   - [W_hh|W_ih] row in 96 scalar float regs; plain C++ FFMA chains so
//     ptxas owns banking/.reuse (the R13 win)
//   - operands hx[buf][b][96], float4 warp-broadcast LDS.128
//   - activation y = A*rcp(1+ex2(S*x))+B in-register (2 MUFU/gate)
//   - quad combine via 3 independent shfl_xor(1,2,3); c tracked redundantly
//     in all 4 lanes of the quad (deterministic) -> gates NEVER touch smem
//   - gq==0 writes h to buf[(t+1)&1]; gq==1 stages x(t+1) there too
//   - double-buffered hx -> single __syncthreads per step
// ---------------------------------------------------------------------------
__global__ __launch_bounds__(256, 2) void fused_lstm_kernel(
    const float* __restrict__ x,    const float* __restrict__ w_ih,
    const float* __restrict__ w_hh, const float* __restrict__ b_ih,
    const float* __restrict__ b_hh, const float* __restrict__ w_fc,
    const float* __restrict__ b_fc, float* __restrict__ out)
{
    __shared__ __align__(16) float hx[2][2][HX_DIM];  // [buf][batch][dim]

    const int tid  = threadIdx.x;
    const int cell = tid >> 2;          // 0..63
    const int gq   = tid & 3;           // 0:i 1:f 2:g 3:o
    const int row  = gq * 64 + cell;    // PyTorch gate order i,f,g,o
    const int B0   = blockIdx.x * 2;

    // ---- weights for row: [W_hh(64) | W_ih(32)] in 96 scalar regs ----
    float w[HX_DIM];
    {
        const float* rh = w_hh + row * H_DIM;
        #pragma unroll
        for (int k = 0; k < H_DIM; k++) w[k] = rh[k];
        const float* ri = w_ih + row * I_DIM;
        #pragma unroll
        for (int i = 0; i < I_DIM; i++) w[H_DIM + i] = ri[i];
    }
    const float bias = b_ih[row] + b_hh[row];

    // ---- per-lane activation constants: y = A*rcp(1 + ex2(S*x)) + B ----
    const float A  = (gq == 2) ? -2.0f       : 1.0f;
    const float S  = (gq == 2) ?  2.0f * L2E : -L2E;
    const float Bc = (gq == 2) ?  1.0f       : 0.0f;

    // ---- x staging: gq==1 lanes (64 of them); batch bq, dim iq ----
    const bool is_stage = (gq == 1);
    const int  bq = cell >> 5, iq = cell & 31;
    const float* sx = x + ((size_t)(B0 + bq) * T_STEPS) * I_DIM + iq;
    float xr0 = 0.f, xr1 = 0.f, xr2 = 0.f;

    // ---- init buf0: h = 0, x(0); preload x(1..3) into the ring ----
    if (tid < 128) hx[0][tid >> 6][tid & 63] = 0.0f;
    if (is_stage) {
        hx[0][bq][H_DIM + iq] = sx[0];
        xr0 = sx[1 * I_DIM];
        xr1 = sx[2 * I_DIM];
        xr2 = sx[3 * I_DIM];
    }
    float c0 = 0.0f, c1 = 0.0f;   // cell state (redundant across quad lanes)
    __syncthreads();

    for (int t = 0; t < T_STEPS; t++) {
        const float4* v0 = (const float4*)hx[t & 1][0];
        const float4* v1 = (const float4*)hx[t & 1][1];

        // ---- scalar matvec: 96-dim [h;x] dots, both batches, split accs ----
        float a0 = bias, a1 = bias;
        float d0 = 0.f,  d1 = 0.f;
        #pragma unroll
        for (int kk = 0; kk < HX_DIM / 8; kk++) {
            float4 p0 = v0[2 * kk];
            float4 p1 = v0[2 * kk + 1];
            float4 q0 = v1[2 * kk];
            float4 q1 = v1[2 * kk + 1];
            const int k = 8 * kk;
            a0 = fmaf(w[k + 0], p0.x, a0); a0 = fmaf(w[k + 1], p0.y, a0);
            a0 = fmaf(w[k + 2], p0.z, a0); a0 = fmaf(w[k + 3], p0.w, a0);
            d0 = fmaf(w[k + 4], p1.x, d0); d0 = fmaf(w[k + 5], p1.y, d0);
            d0 = fmaf(w[k + 6], p1.z, d0); d0 = fmaf(w[k + 7], p1.w, d0);
            a1 = fmaf(w[k + 0], q0.x, a1); a1 = fmaf(w[k + 1], q0.y, a1);
            a1 = fmaf(w[k + 2], q0.z, a1); a1 = fmaf(w[k + 3], q0.w, a1);
            d1 = fmaf(w[k + 4], q1.x, d1); d1 = fmaf(w[k + 5], q1.y, d1);
            d1 = fmaf(w[k + 6], q1.z, d1); d1 = fmaf(w[k + 7], q1.w, d1);
        }
        float G0 = a0 + d0;
        float G1 = a1 + d1;

        // ---- in-register activation (2 MUFU + 2 alu per batch) ----
        float y0 = A * rcpf(1.0f + ex2f(S * G0)) + Bc;
        float y1 = A * rcpf(1.0f + ex2f(S * G1)) + Bc;
        u64 y = pack2(y0, y1);

        // ---- quad combine: 3 independent shfls (lanes 0=i 1=f 2=g 3=o) ----
        u64 fv = __shfl_xor_sync(0xffffffffu, y, 1);  // gq0 view: f
        u64 gv = __shfl_xor_sync(0xffffffffu, y, 2);  // gq0 view: g
        u64 ov = __shfl_xor_sync(0xffffffffu, y, 3);  // gq0 view: o
        float f0, f1, g0, g1, o0, o1;
        unpack2(fv, f0, f1);
        unpack2(gv, g0, g1);
        unpack2(ov, o0, o1);
        c0 = f0 * c0 + y0 * g0;          // valid on gq==0 (redundant elsewhere)
        c1 = f1 * c1 + y1 * g1;
        float t0 = 1.0f - 2.0f * rcpf(1.0f + ex2f(2.0f * L2E * c0));
        float t1 = 1.0f - 2.0f * rcpf(1.0f + ex2f(2.0f * L2E * c1));
        float h0 = o0 * t0;
        float h1 = o1 * t1;

        // ---- write next buffer; x stage rides the same phase ----
        float* nb0 = hx[(t + 1) & 1][0];
        float* nb1 = hx[(t + 1) & 1][1];
        if (gq == 0) {
            nb0[cell] = h0;
            nb1[cell] = h1;
        } else if (is_stage) {
            if (t + 1 < T_STEPS) hx[(t + 1) & 1][bq][H_DIM + iq] = xr0;
            xr0 = xr1; xr1 = xr2;
            if (t + 4 < T_STEPS) xr2 = sx[(size_t)(t + 4) * I_DIM];
        }

        __syncthreads();   // SINGLE barrier per step
    }

    // ---- final FC: h_last lives in buf[0] (T even) ----
    if (tid < 2 * NT) {
        int b = tid >> 3, n = tid & 7;
        float s = b_fc[n];
        const float* wf = w_fc + n * H_DIM;
        #pragma unroll
        for (int k = 0; k < H_DIM; k++) s += hx[0][b][k] * wf[k];
        out[(B0 + b) * NT + n] = s;
    }
}

// ---------------------------------------------------------------------------
extern "C" void kernel_launch(void* const* d_in, const int* in_sizes, int n_in,
                              void* d_out, int out_size)
{
    const float* x    = (const float*)d_in[0];
    const float* w_ih = (const float*)d_in[1];
    const float* w_hh = (const float*)d_in[2];
    const float* b_ih = (const float*)d_in[3];
    const float* b_hh = (const float*)d_in[4];
    const float* w_fc = (const float*)d_in[5];
    const float* b_fc = (const float*)d_in[6];
    float* out = (float*)d_out;

    (void)in_sizes; (void)n_in; (void)out_size;

    fused_lstm_kernel<<<B_TOTAL / 2, 256>>>(x, w_ih, w_hh, b_ih, b_hh,
                                            w_fc, b_fc, out);
}

// round 15
// speedup vs baseline: 1.1348x; 1.1348x over previous
#include <cuda_runtime.h>

// Problem constants
#define T_STEPS 512
#define B_TOTAL 512
#define I_DIM   32
#define H_DIM   64
#define G_DIM   256   // 4*H
#define NT      8     // num tickers

__device__ __forceinline__ float ex2f(float x) {
    float r;
    asm("ex2.approx.f32 %0, %1;" : "=f"(r) : "f"(x));
    return r;
}
__device__ __forceinline__ float rcpf(float x) {
    float r;
    asm("rcp.approx.f32 %0, %1;" : "=f"(r) : "f"(x));
    return r;
}
#define L2E 1.4426950408889634f
__device__ __forceinline__ float sigm_fast(float x) {       // 1/(1+e^-x)
    return rcpf(1.0f + ex2f(-L2E * x));
}
__device__ __forceinline__ float tanh_fast2(float x) {      // 1 - 2/(e^2x+1)
    return 1.0f - 2.0f * rcpf(1.0f + ex2f(2.0f * L2E * x));
}

// ---------------------------------------------------------------------------
// Fused LSTM, x-overlap edition (R13 + x-projection in the elementwise window)
// 256 CTAs x 256 threads, 2 batches/CTA, 2 CTAs/SM.
// Thread (q = tid&3, cellr = tid>>2) owns gate row q*64+cellr:
//   - W_hh row (64) + W_ih row (32) in 96 scalar regs; plain C++ FFMA chains
//   - per-step matvec = h(t)-part ONLY (128 FFMA/thread), seeded from the
//     xacc register computed one step earlier
//   - xacc(t+1) (64 FFMA/thread) computed pre-barrier-A by threads 0..127 and
//     POST-barrier-A by threads 128..255 -> fills the elementwise window
//   - gates stored quad-packed: gates4[b][cellr*4+q] -> elementwise reads one
//     conflict-free LDS.128 (i,f,g,o adjacent)
//   - x in a 2-slot smem ring xs[(t)&1]; slot writes (post-barA, x(t+2)) are
//     barrier-separated from all reads; depth-2 LDG register prefetch
//   - elementwise: threads 0..127 (concentrated -> MUFU instr count minimal)
// ---------------------------------------------------------------------------
__global__ __launch_bounds__(256, 2) void fused_lstm_kernel(
    const float* __restrict__ x,    const float* __restrict__ w_ih,
    const float* __restrict__ w_hh, const float* __restrict__ b_ih,
    const float* __restrict__ b_hh, const float* __restrict__ w_fc,
    const float* __restrict__ b_fc, float* __restrict__ out)
{
    __shared__ __align__(16) float hx[2][H_DIM];      // [batch][cell] h state
    __shared__ __align__(16) float xs[2][2][I_DIM];   // [slot][batch][i]
    __shared__ __align__(16) float gates4[2][G_DIM];  // [batch][cellr*4+q]

    const int tid   = threadIdx.x;
    const int q     = tid & 3;          // gate quad: 0:i 1:f 2:g 3:o
    const int cellr = tid >> 2;         // 0..63
    const int row   = q * 64 + cellr;   // PyTorch gate order i,f,g,o
    const int B0    = blockIdx.x * 2;

    // ---- weights: [W_hh(64) | W_ih(32)] for row, in 96 scalar regs ----
    float w[96];
    {
        const float* rh = w_hh + row * H_DIM;
        #pragma unroll
        for (int k = 0; k < H_DIM; k++) w[k] = rh[k];
        const float* ri = w_ih + row * I_DIM;
        #pragma unroll
        for (int i = 0; i < I_DIM; i++) w[H_DIM + i] = ri[i];
    }
    const float bias = b_ih[row] + b_hh[row];

    // ---- elementwise identity: threads 0..127 own (be, ke) ----
    const int be = tid >> 6;            // valid for tid < 128
    const int ke = tid & 63;
    float c_val = 0.0f;

    // ---- staging identity: threads 128..191 stage x (bq, iq) ----
    const int  st = tid - 128;
    const bool is_stage = (st >= 0) && (st < 64);
    const int  bq = (st >> 5) & 1, iq = st & 31;
    const float* sx = x + ((size_t)(B0 + bq) * T_STEPS) * I_DIM + iq;
    float xr0 = 0.f, xr1 = 0.f;

    // ---- init: h = 0; x(0)->slot0, x(1)->slot1; x(2),x(3) in regs ----
    if (tid < 128) hx[be][ke] = 0.0f;
    if (is_stage) {
        xs[0][bq][iq] = sx[0];
        xs[1][bq][iq] = sx[1 * I_DIM];
        xr0 = sx[2 * I_DIM];
        xr1 = sx[3 * I_DIM];
    }
    __syncthreads();

    // ---- xacc for t = 0 (all threads; includes bias) ----
    float xa0 = bias, xa1 = bias;
    {
        const float4* xv0 = (const float4*)xs[0][0];
        const float4* xv1 = (const float4*)xs[0][1];
        #pragma unroll
        for (int kk = 0; kk < I_DIM / 4; kk++) {
            float4 p = xv0[kk];
            float4 r = xv1[kk];
            const int k = H_DIM + 4 * kk;
            xa0 = fmaf(w[k+0], p.x, xa0); xa0 = fmaf(w[k+1], p.y, xa0);
            xa0 = fmaf(w[k+2], p.z, xa0); xa0 = fmaf(w[k+3], p.w, xa0);
            xa1 = fmaf(w[k+0], r.x, xa1); xa1 = fmaf(w[k+1], r.y, xa1);
            xa1 = fmaf(w[k+2], r.z, xa1); xa1 = fmaf(w[k+3], r.w, xa1);
        }
    }

    for (int t = 0; t < T_STEPS; t++) {
        // ---- h-part matvec: 64-dim dots, both batches, split accs ----
        const float4* v0 = (const float4*)hx[0];
        const float4* v1 = (const float4*)hx[1];
        float a0 = xa0, a1 = xa1;
        float d0 = 0.f, d1 = 0.f;
        #pragma unroll
        for (int kk = 0; kk < H_DIM / 8; kk++) {
            float4 p0 = v0[2 * kk];
            float4 p1 = v0[2 * kk + 1];
            float4 q0 = v1[2 * kk];
            float4 q1 = v1[2 * kk + 1];
            const int k = 8 * kk;
            a0 = fmaf(w[k+0], p0.x, a0); a0 = fmaf(w[k+1], p0.y, a0);
            a0 = fmaf(w[k+2], p0.z, a0); a0 = fmaf(w[k+3], p0.w, a0);
            d0 = fmaf(w[k+4], p1.x, d0); d0 = fmaf(w[k+5], p1.y, d0);
            d0 = fmaf(w[k+6], p1.z, d0); d0 = fmaf(w[k+7], p1.w, d0);
            a1 = fmaf(w[k+0], q0.x, a1); a1 = fmaf(w[k+1], q0.y, a1);
            a1 = fmaf(w[k+2], q0.z, a1); a1 = fmaf(w[k+3], q0.w, a1);
            d1 = fmaf(w[k+4], q1.x, d1); d1 = fmaf(w[k+5], q1.y, d1);
            d1 = fmaf(w[k+6], q1.z, d1); d1 = fmaf(w[k+7], q1.w, d1);
        }
        gates4[0][cellr * 4 + q] = a0 + d0;
        gates4[1][cellr * 4 + q] = a1 + d1;

        // ---- EARLY xacc(t+1): threads 0..127, pre-barrier ----
        if (tid < 128) {
            xa0 = bias; xa1 = bias;
            if (t + 1 < T_STEPS) {
                const float4* xv0 = (const float4*)xs[(t + 1) & 1][0];
                const float4* xv1 = (const float4*)xs[(t + 1) & 1][1];
                #pragma unroll
                for (int kk = 0; kk < I_DIM / 4; kk++) {
                    float4 p = xv0[kk];
                    float4 r = xv1[kk];
                    const int k = H_DIM + 4 * kk;
                    xa0 = fmaf(w[k+0], p.x, xa0); xa0 = fmaf(w[k+1], p.y, xa0);
                    xa0 = fmaf(w[k+2], p.z, xa0); xa0 = fmaf(w[k+3], p.w, xa0);
                    xa1 = fmaf(w[k+0], r.x, xa1); xa1 = fmaf(w[k+1], r.y, xa1);
                    xa1 = fmaf(w[k+2], r.z, xa1); xa1 = fmaf(w[k+3], r.w, xa1);
                }
            }
        }

        __syncthreads();   // A: gates visible; h/x reads of step t complete

        if (tid < 128) {
            // ---- elementwise: ONE LDS.128 yields i,f,g,o ----
            float4 gt = *(const float4*)&gates4[be][ke * 4];
            float i_a = sigm_fast (gt.x);
            float f_a = sigm_fast (gt.y);
            float g_a = tanh_fast2(gt.z);
            float o_a = sigm_fast (gt.w);
            c_val = f_a * c_val + i_a * g_a;
            hx[be][ke] = o_a * tanh_fast2(c_val);
        } else {
            // ---- stagers: write x(t+2) into slot t&1; refill ring ----
            if (is_stage) {
                if (t + 2 < T_STEPS) xs[t & 1][bq][iq] = xr0;
                xr0 = xr1;
                if (t + 4 < T_STEPS) xr1 = sx[(size_t)(t + 4) * I_DIM];
            }
            // ---- LATE xacc(t+1): fills the elementwise window with fma ----
            xa0 = bias; xa1 = bias;
            if (t + 1 < T_STEPS) {
                const float4* xv0 = (const float4*)xs[(t + 1) & 1][0];
                const float4* xv1 = (const float4*)xs[(t + 1) & 1][1];
                #pragma unroll
                for (int kk = 0; kk < I_DIM / 4; kk++) {
                    float4 p = xv0[kk];
                    float4 r = xv1[kk];
                    const int k = H_DIM + 4 * kk;
                    xa0 = fmaf(w[k+0], p.x, xa0); xa0 = fmaf(w[k+1], p.y, xa0);
                    xa0 = fmaf(w[k+2], p.z, xa0); xa0 = fmaf(w[k+3], p.w, xa0);
                    xa1 = fmaf(w[k+0], r.x, xa1); xa1 = fmaf(w[k+1], r.y, xa1);
                    xa1 = fmaf(w[k+2], r.z, xa1); xa1 = fmaf(w[k+3], r.w, xa1);
                }
            }
        }

        __syncthreads();   // B: h(t+1), x slots visible
    }

    // ---- final FC: out[b][n] = h_last[b] . w_fc[n] + b_fc[n] ----
    if (tid < 2 * NT) {
        int b = tid >> 3, n = tid & 7;
        float s = b_fc[n];
        const float* wf = w_fc + n * H_DIM;
        #pragma unroll
        for (int k = 0; k < H_DIM; k++) s += hx[b][k] * wf[k];
        out[(B0 + b) * NT + n] = s;
    }
}

// ---------------------------------------------------------------------------
extern "C" void kernel_launch(void* const* d_in, const int* in_sizes, int n_in,
                              void* d_out, int out_size)
{
    const float* x    = (const float*)d_in[0];
    const float* w_ih = (const float*)d_in[1];
    const float* w_hh = (const float*)d_in[2];
    const float* b_ih = (const float*)d_in[3];
    const float* b_hh = (const float*)d_in[4];
    const float* w_fc = (const float*)d_in[5];
    const float* b_fc = (const float*)d_in[6];
    float* out = (float*)d_out;

    (void)in_sizes; (void)n_in; (void)out_size;

    fused_lstm_kernel<<<B_TOTAL / 2, 256>>>(x, w_ih, w_hh, b_ih, b_hh,
                                            w_fc, b_fc, out);
}

// round 16
// speedup vs baseline: 1.4409x; 1.2697x over previous
#include <cuda_runtime.h>
#include <cuda_fp16.h>

// Problem constants
#define T_STEPS 512
#define B_TOTAL 512
#define I_DIM   32
#define H_DIM   64
#define G_DIM   256   // 4*H
#define NT      8     // num tickers

__device__ __forceinline__ float ex2f(float x) {
    float r;
    asm("ex2.approx.f32 %0, %1;" : "=f"(r) : "f"(x));
    return r;
}
__device__ __forceinline__ float rcpf(float x) {
    float r;
    asm("rcp.approx.f32 %0, %1;" : "=f"(r) : "f"(x));
    return r;
}
#define L2E 1.4426950408889634f
__device__ __forceinline__ float sigm_fast(float x) {       // 1/(1+e^-x)
    return rcpf(1.0f + ex2f(-L2E * x));
}
__device__ __forceinline__ float tanh_fast2(float x) {      // 1 - 2/(e^2x+1)
    return 1.0f - 2.0f * rcpf(1.0f + ex2f(2.0f * L2E * x));
}

// ---------------------------------------------------------------------------
// Fused LSTM = R13 (best, 592us) + fp16 x-projection + quad-packed gates.
// 256 CTAs x 256 threads, 2 batches/CTA, 2 CTAs/SM.
// Thread (q = tid&3, cellr = tid>>2) owns gate row q*64+cellr:
//   - W_hh row: 64 fp32 regs, scalar FFMA chains (ptxas-scheduled - R13 win)
//   - W_ih row: 16 half2 regs; x staged in smem as __half; x-dot via HFMA2
//     (2 MACs/instr, rt2, no RF-bank penalty) -> -13.5% fma-pipe instrs,
//     -16 weight regs (scheduling slack under the 128 cap)
//   - h-path stays FULL fp32: fp16 error enters only via x (non-recurrent,
//     decays through the forget gate) -> rel_err ~1e-5..1e-4
//   - gates quad-packed gates4[b][cellr*4+q]: elementwise reads ONE LDS.128
//   - elementwise concentrated in threads 0..127 (minimal MUFU instrs);
//     x staged by threads 128..191 via depth-4 register prefetch ring
// ---------------------------------------------------------------------------
__global__ __launch_bounds__(256, 2) void fused_lstm_kernel(
    const float* __restrict__ x,    const float* __restrict__ w_ih,
    const float* __restrict__ w_hh, const float* __restrict__ b_ih,
    const float* __restrict__ b_hh, const float* __restrict__ w_fc,
    const float* __restrict__ b_fc, float* __restrict__ out)
{
    __shared__ __align__(16) float  hx[2][H_DIM];     // [batch][cell] h (fp32)
    __shared__ __align__(16) __half xsm[2][I_DIM];    // [batch][i] x (fp16)
    __shared__ __align__(16) float  gates4[2][G_DIM]; // [batch][cellr*4+q]

    const int tid   = threadIdx.x;
    const int q     = tid & 3;          // gate: 0:i 1:f 2:g 3:o
    const int cellr = tid >> 2;         // 0..63
    const int row   = q * 64 + cellr;   // PyTorch gate order i,f,g,o
    const int B0    = blockIdx.x * 2;

    // ---- W_hh row in 64 fp32 regs; W_ih row in 16 half2 regs ----
    float wh[H_DIM];
    {
        const float* rh = w_hh + row * H_DIM;
        #pragma unroll
        for (int k = 0; k < H_DIM; k++) wh[k] = rh[k];
    }
    __half2 wx[I_DIM / 2];
    {
        const float* ri = w_ih + row * I_DIM;
        #pragma unroll
        for (int i = 0; i < I_DIM / 2; i++)
            wx[i] = __floats2half2_rn(ri[2 * i], ri[2 * i + 1]);
    }
    const float bias = b_ih[row] + b_hh[row];

    // ---- elementwise identity: threads 0..127 own (be, ke) ----
    const int be = tid >> 6;            // valid for tid < 128
    const int ke = tid & 63;
    float c_val = 0.0f;

    // ---- staging identity: threads 128..191 stage x (bq, iq) ----
    const int  st = tid - 128;
    const bool is_stage = (st >= 0) && (st < 64);
    const int  bq = (st >> 5) & 1, iq = st & 31;
    const float* sx = x + ((size_t)(B0 + bq) * T_STEPS) * I_DIM + iq;
    float xr0 = 0.f, xr1 = 0.f, xr2 = 0.f;

    // ---- init: h = 0, x(0) staged (fp16), x(1..3) in the reg ring ----
    if (tid < 128) hx[be][ke] = 0.0f;
    if (is_stage) {
        xsm[bq][iq] = __float2half(sx[0]);
        xr0 = sx[1 * I_DIM];
        xr1 = sx[2 * I_DIM];
        xr2 = sx[3 * I_DIM];
    }
    __syncthreads();

    const float4* v0  = (const float4*)hx[0];
    const float4* v1  = (const float4*)hx[1];
    const float4* xv0 = (const float4*)xsm[0];   // 32 half = 4 float4
    const float4* xv1 = (const float4*)xsm[1];

    for (int t = 0; t < T_STEPS; t++) {
        // ---- h-part: 64-dim fp32 dots, both batches, split accumulators ----
        float a0 = bias, a1 = bias;
        float d0 = 0.f,  d1 = 0.f;
        #pragma unroll
        for (int kk = 0; kk < H_DIM / 8; kk++) {
            float4 p0 = v0[2 * kk];
            float4 p1 = v0[2 * kk + 1];
            float4 q0 = v1[2 * kk];
            float4 q1 = v1[2 * kk + 1];
            const int k = 8 * kk;
            a0 = fmaf(wh[k+0], p0.x, a0); a0 = fmaf(wh[k+1], p0.y, a0);
            a0 = fmaf(wh[k+2], p0.z, a0); a0 = fmaf(wh[k+3], p0.w, a0);
            d0 = fmaf(wh[k+4], p1.x, d0); d0 = fmaf(wh[k+5], p1.y, d0);
            d0 = fmaf(wh[k+6], p1.z, d0); d0 = fmaf(wh[k+7], p1.w, d0);
            a1 = fmaf(wh[k+0], q0.x, a1); a1 = fmaf(wh[k+1], q0.y, a1);
            a1 = fmaf(wh[k+2], q0.z, a1); a1 = fmaf(wh[k+3], q0.w, a1);
            d1 = fmaf(wh[k+4], q1.x, d1); d1 = fmaf(wh[k+5], q1.y, d1);
            d1 = fmaf(wh[k+6], q1.z, d1); d1 = fmaf(wh[k+7], q1.w, d1);
        }

        // ---- x-part: 32-dim fp16 dots via HFMA2 (16/batch), split chains ----
        __half2 xa0 = __float2half2_rn(0.f), xb0 = __float2half2_rn(0.f);
        __half2 xa1 = __float2half2_rn(0.f), xb1 = __float2half2_rn(0.f);
        #pragma unroll
        for (int kk = 0; kk < 4; kk++) {
            float4 P = xv0[kk];
            float4 Q = xv1[kk];
            const __half2* ph = (const __half2*)&P;   // 4 half2
            const __half2* qh = (const __half2*)&Q;
            xa0 = __hfma2(wx[4*kk+0], ph[0], xa0);
            xb0 = __hfma2(wx[4*kk+1], ph[1], xb0);
            xa0 = __hfma2(wx[4*kk+2], ph[2], xa0);
            xb0 = __hfma2(wx[4*kk+3], ph[3], xb0);
            xa1 = __hfma2(wx[4*kk+0], qh[0], xa1);
            xb1 = __hfma2(wx[4*kk+1], qh[1], xb1);
            xa1 = __hfma2(wx[4*kk+2], qh[2], xa1);
            xb1 = __hfma2(wx[4*kk+3], qh[3], xb1);
        }
        float2 fa0 = __half22float2(xa0), fb0 = __half22float2(xb0);
        float2 fa1 = __half22float2(xa1), fb1 = __half22float2(xb1);
        float G0 = (a0 + d0) + ((fa0.x + fa0.y) + (fb0.x + fb0.y));
        float G1 = (a1 + d1) + ((fa1.x + fa1.y) + (fb1.x + fb1.y));

        gates4[0][cellr * 4 + q] = G0;   // consecutive addresses across tid
        gates4[1][cellr * 4 + q] = G1;

        __syncthreads();   // A: gates visible; h/x reads of step t complete

        if (tid < 128) {
            // ---- elementwise: ONE LDS.128 yields i,f,g,o ----
            float4 gt = *(const float4*)&gates4[be][ke * 4];
            float i_a = sigm_fast (gt.x);
            float f_a = sigm_fast (gt.y);
            float g_a = tanh_fast2(gt.z);
            float o_a = sigm_fast (gt.w);
            c_val = f_a * c_val + i_a * g_a;
            hx[be][ke] = o_a * tanh_fast2(c_val);
        } else if (is_stage) {
            // ---- stage x(t+1) (fp16) from the ring; refill with x(t+4) ----
            if (t + 1 < T_STEPS) xsm[bq][iq] = __float2half(xr0);
            xr0 = xr1; xr1 = xr2;
            if (t + 4 < T_STEPS) xr2 = sx[(size_t)(t + 4) * I_DIM];
        }

        __syncthreads();   // B: h(t+1), x(t+1) visible
    }

    // ---- final FC: out[b][n] = h_last[b] . w_fc[n] + b_fc[n] ----
    if (tid < 2 * NT) {
        int b = tid >> 3, n = tid & 7;
        float s = b_fc[n];
        const float* wf = w_fc + n * H_DIM;
        #pragma unroll
        for (int k = 0; k < H_DIM; k++) s += hx[b][k] * wf[k];
        out[(B0 + b) * NT + n] = s;
    }
}

// ---------------------------------------------------------------------------
extern "C" void kernel_launch(void* const* d_in, const int* in_sizes, int n_in,
                              void* d_out, int out_size)
{
    const float* x    = (const float*)d_in[0];
    const float* w_ih = (const float*)d_in[1];
    const float* w_hh = (const float*)d_in[2];
    const float* b_ih = (const float*)d_in[3];
    const float* b_hh = (const float*)d_in[4];
    const float* w_fc = (const float*)d_in[5];
    const float* b_fc = (const float*)d_in[6];
    float* out = (float*)d_out;

    (void)in_sizes; (void)n_in; (void)out_size;

    fused_lstm_kernel<<<B_TOTAL / 2, 256>>>(x, w_ih, w_hh, b_ih, b_hh,
                                            w_fc, b_fc, out);
}